// round 3
// baseline (speedup 1.0000x reference)
#include <cuda_runtime.h>
#include <math.h>

#define BB 512
#define NN 64
#define MH 128

typedef unsigned long long u64;

// ---- scratch (allocation-free) ----
__device__ __align__(16) float  g_HT[BB * MH * NN];   // [b][k][r] transposed H (16MB)
__device__ __align__(16) float2 g_WfD[MH * MH];       // (w,w)-dup: phi_w1 @ psi_w0[3:]
__device__ __align__(16) float2 g_W1D[MH * MH];       // (w,w)-dup: psi_w1
__device__ float g_c0[MH];                            // psi_b0 + 63*phi_b1@psi_w0[3:]
__device__ float g_sp;                                // softplus(bf_scale_raw)

// ---- f32x2 helpers (sm_100a packed fp32) ----
__device__ __forceinline__ u64 pk(float a, float b) {
    u64 r; asm("mov.b64 %0, {%1,%2};" : "=l"(r) : "f"(a), "f"(b)); return r;
}
__device__ __forceinline__ float2 upk(u64 a) {
    float2 r; asm("mov.b64 {%0,%1}, %2;" : "=f"(r.x), "=f"(r.y) : "l"(a)); return r;
}
__device__ __forceinline__ u64 fma2(u64 a, u64 b, u64 c) {
    u64 d; asm("fma.rn.f32x2 %0, %1, %2, %3;" : "=l"(d) : "l"(a), "l"(b), "l"(c)); return d;
}
__device__ __forceinline__ u64 add2(u64 a, u64 b) {
    u64 d; asm("add.rn.f32x2 %0, %1, %2;" : "=l"(d) : "l"(a), "l"(b)); return d;
}
__device__ __forceinline__ float tanh_apx(float v) {
    float y; asm("tanh.approx.f32 %0, %1;" : "=f"(y) : "f"(v)); return y;
}
__device__ __forceinline__ float silu_f(float q) {
    float qh = 0.5f * q;
    float th = tanh_apx(qh);
    return fmaf(qh, th, qh);
}

// ---------------------------------------------------------------------------
// Kernel 0: precompute fused/duplicated weights + folded biases + softplus.
// ---------------------------------------------------------------------------
__global__ __launch_bounds__(128) void precompute_kernel(
    const float* __restrict__ phi_w1, const float* __restrict__ phi_b1,
    const float* __restrict__ psi_w0, const float* __restrict__ psi_b0,
    const float* __restrict__ psi_w1, const float* __restrict__ bf_scale_raw)
{
    __shared__ float row[MH];
    int t = threadIdx.x;
    int k = blockIdx.x;
    const float* src = (k < MH) ? (phi_w1 + k * MH) : phi_b1;
    row[t] = src[t];
    __syncthreads();

    float a0 = 0.f, a1 = 0.f, a2 = 0.f, a3 = 0.f;
    #pragma unroll 8
    for (int m = 0; m < MH; m += 4) {
        a0 = fmaf(row[m + 0], psi_w0[(3 + m + 0) * MH + t], a0);
        a1 = fmaf(row[m + 1], psi_w0[(3 + m + 1) * MH + t], a1);
        a2 = fmaf(row[m + 2], psi_w0[(3 + m + 2) * MH + t], a2);
        a3 = fmaf(row[m + 3], psi_w0[(3 + m + 3) * MH + t], a3);
    }
    float acc = (a0 + a1) + (a2 + a3);
    if (k < MH) {
        g_WfD[k * MH + t] = make_float2(acc, acc);
        float w1 = psi_w1[k * MH + t];
        g_W1D[k * MH + t] = make_float2(w1, w1);
    } else {
        g_c0[t] = psi_b0[t] + 63.0f * acc;
        if (t == 0) {
            float v = bf_scale_raw[0];
            g_sp = (v > 20.0f) ? v : log1pf(__expf(v));
        }
    }
}

// ---------------------------------------------------------------------------
// phi kernel: 1024 blocks = (batch, 32-row half) x 256 threads.
// Warp w owns rows R0 + w*4 .. +3; lane l owns channels 4l..4l+3.
// Packed over row-pairs: r1 stored duplicated (r1,r1) in shared -> free pairs.
// Writes H TRANSPOSED to g_HT[b][k][r] via per-lane STG.128 (lane owns the
// 4-row column of each of its channels).
// ---------------------------------------------------------------------------
__global__ __launch_bounds__(256, 3) void phi_kernel(
    const float* __restrict__ x,
    const float* __restrict__ W0, const float* __restrict__ b0)
{
    __shared__ __align__(16) float vs[NN * MH];   // 32KB: halved v'_j[k]
    __shared__ __align__(16) u64 r1d[NN * 32];    // 16KB: (r1,r1) [j][il]

    int bh = blockIdx.x;
    int b = bh >> 1, half = bh & 1;
    int R0 = half * 32;
    int t = threadIdx.x, w = t >> 5, l = t & 31;
    int w4 = w * 4, kc = l * 4;
    const float* xb = x + b * (NN * 3);

    // v'_j[k] = 0.5 * sum_d xj_d * (W0[3+d,k] - W0[6+d,k])
    for (int idx = t; idx < NN * MH; idx += 256) {
        int j = idx >> 7, k = idx & 127;
        float xj0 = xb[j * 3 + 0], xj1 = xb[j * 3 + 1], xj2 = xb[j * 3 + 2];
        float vv = xj0 * (W0[3 * MH + k] - W0[6 * MH + k]);
        vv = fmaf(xj1, W0[4 * MH + k] - W0[7 * MH + k], vv);
        vv = fmaf(xj2, W0[5 * MH + k] - W0[8 * MH + k], vv);
        vs[idx] = 0.5f * vv;
    }
    // r1d[j][il] = (r1, r1) for i = R0+il
    for (int idx = t; idx < NN * 32; idx += 256) {
        int j = idx >> 5, il = idx & 31;
        int i = R0 + il;
        float d0 = xb[i * 3 + 0] - xb[j * 3 + 0];
        float d1 = xb[i * 3 + 1] - xb[j * 3 + 1];
        float d2 = xb[i * 3 + 2] - xb[j * 3 + 2];
        float r1 = sqrtf(fmaf(d0, d0, fmaf(d1, d1, fmaf(d2, d2, 1e-12f))));
        r1d[idx] = pk(r1, r1);
    }

    // per-lane halved channel weights (packed over channel pairs)
    u64 w9p[2], w10p[2], up[4][2];
    float w9s[4], w10s[4];
    {
        float ws0[4], ws1[4], ws2[4], bh4[4];
        #pragma unroll
        for (int c = 0; c < 4; c++) {
            int k = kc + c;
            ws0[c] = 0.5f * (W0[0 * MH + k] + W0[6 * MH + k]);
            ws1[c] = 0.5f * (W0[1 * MH + k] + W0[7 * MH + k]);
            ws2[c] = 0.5f * (W0[2 * MH + k] + W0[8 * MH + k]);
            w9s[c]  = 0.5f * W0[9 * MH + k];
            w10s[c] = 0.5f * W0[10 * MH + k];
            bh4[c] = 0.5f * b0[k];
        }
        w9p[0]  = pk(w9s[0], w9s[1]);   w9p[1]  = pk(w9s[2], w9s[3]);
        w10p[0] = pk(w10s[0], w10s[1]); w10p[1] = pk(w10s[2], w10s[3]);
        #pragma unroll
        for (int rr = 0; rr < 4; rr++) {
            int i = R0 + w4 + rr;
            float xi0 = xb[i * 3 + 0], xi1 = xb[i * 3 + 1], xi2 = xb[i * 3 + 2];
            float uu[4];
            #pragma unroll
            for (int c = 0; c < 4; c++)
                uu[c] = fmaf(xi2, ws2[c],
                        fmaf(xi1, ws1[c], fmaf(xi0, ws0[c], bh4[c])));
            up[rr][0] = pk(uu[0], uu[1]);
            up[rr][1] = pk(uu[2], uu[3]);
        }
    }
    __syncthreads();

    float acc[4][4];
    #pragma unroll
    for (int rr = 0; rr < 4; rr++)
        #pragma unroll
        for (int c = 0; c < 4; c++) acc[rr][c] = 0.0f;

    u64 negeps = pk(-1e-12f, -1e-12f);

    #pragma unroll 1
    for (int j = 0; j < NN; j++) {
        ulonglong2 p01 = *reinterpret_cast<const ulonglong2*>(&r1d[j * 32 + w4]);
        ulonglong2 p23 = *reinterpret_cast<const ulonglong2*>(&r1d[j * 32 + w4 + 2]);
        u64 r1p[4] = {p01.x, p01.y, p23.x, p23.y};
        u64 r2p[4];
        #pragma unroll
        for (int rr = 0; rr < 4; rr++)
            r2p[rr] = fma2(r1p[rr], r1p[rr], negeps);
        float4 v4 = *(const float4*)&vs[j * MH + kc];
        u64 vp[2] = {pk(v4.x, v4.y), pk(v4.z, v4.w)};

        #pragma unroll
        for (int rr = 0; rr < 4; rr++) {
            #pragma unroll
            for (int p = 0; p < 2; p++) {
                u64 tt = add2(up[rr][p], vp[p]);
                tt = fma2(r2p[rr], w10p[p], tt);
                tt = fma2(r1p[rr], w9p[p], tt);
                float2 q = upk(tt);
                float t0 = tanh_apx(q.x);
                float t1 = tanh_apx(q.y);
                acc[rr][2 * p]     = fmaf(q.x, t0, acc[rr][2 * p] + q.x);
                acc[rr][2 * p + 1] = fmaf(q.y, t1, acc[rr][2 * p + 1] + q.y);
            }
        }
    }

    // subtract diagonal term (mirrors in-loop op order exactly -> same rounding)
    #pragma unroll
    for (int rr = 0; rr < 4; rr++) {
        int ig = R0 + w4 + rr;
        float r1 = upk(r1d[ig * 32 + w4 + rr]).x;
        float r2 = fmaf(r1, r1, -1e-12f);
        float4 v4 = *(const float4*)&vs[ig * MH + kc];
        float vv[4] = {v4.x, v4.y, v4.z, v4.w};
        float2 u01 = upk(up[rr][0]), u23 = upk(up[rr][1]);
        float uu[4] = {u01.x, u01.y, u23.x, u23.y};
        #pragma unroll
        for (int c = 0; c < 4; c++) {
            float tq = uu[c] + vv[c];
            tq = fmaf(r2, w10s[c], tq);
            float q = fmaf(r1, w9s[c], tq);
            float th = tanh_apx(q);
            acc[rr][c] -= fmaf(q, th, q);
        }
    }

    // store H transposed: lane owns the 4-row column of each of its channels
    #pragma unroll
    for (int c = 0; c < 4; c++) {
        float4 o = make_float4(acc[0][c], acc[1][c], acc[2][c], acc[3][c]);
        *(float4*)&g_HT[((size_t)b * MH + kc + c) * NN + R0 + w4] = o;
    }
}

// ---------------------------------------------------------------------------
// psi kernel: 512 blocks x 256 threads. Warp w owns rows r0=w*8..+7 (4 row-
// pairs, packed), lane l owns output channels 4l..4l+3.
// layer A: acc += HT-rowpair (LDG.64, broadcast) * dup-weight (LDG.64)
// layer B: via transposed smem h1 (sbT[k][66], warp-private columns)
// ---------------------------------------------------------------------------
__global__ __launch_bounds__(256, 3) void psi_kernel(
    const float* __restrict__ x,
    const float* __restrict__ psi_w0, const float* __restrict__ psi_b1,
    const float* __restrict__ psi_w2, const float* __restrict__ psi_b2,
    float* __restrict__ out)
{
    __shared__ __align__(16) float sbT[MH * 66];   // 33KB transposed h1

    int b = blockIdx.x, t = threadIdx.x, w = t >> 5, l = t & 31;
    int r0 = w * 8, kc = l * 4;
    const float* xb = x + b * (NN * 3);

    u64 acc[4][4];

    // init: c0 + x @ psi_w0[0:3], packed over row pairs
    {
        float4 wc = *(const float4*)&g_c0[kc];
        float4 p0 = *(const float4*)&psi_w0[0 * MH + kc];
        float4 p1 = *(const float4*)&psi_w0[1 * MH + kc];
        float4 p2 = *(const float4*)&psi_w0[2 * MH + kc];
        float cw[4] = {wc.x, wc.y, wc.z, wc.w};
        float q0[4] = {p0.x, p0.y, p0.z, p0.w};
        float q1[4] = {p1.x, p1.y, p1.z, p1.w};
        float q2[4] = {p2.x, p2.y, p2.z, p2.w};
        #pragma unroll
        for (int rp = 0; rp < 4; rp++) {
            int ra = r0 + 2 * rp, rb = ra + 1;
            float a0 = xb[ra * 3 + 0], a1 = xb[ra * 3 + 1], a2 = xb[ra * 3 + 2];
            float b0v = xb[rb * 3 + 0], b1v = xb[rb * 3 + 1], b2v = xb[rb * 3 + 2];
            #pragma unroll
            for (int c = 0; c < 4; c++) {
                float sa = fmaf(a2, q2[c], fmaf(a1, q1[c], fmaf(a0, q0[c], cw[c])));
                float sb = fmaf(b2v, q2[c], fmaf(b1v, q1[c], fmaf(b0v, q0[c], cw[c])));
                acc[rp][c] = pk(sa, sb);
            }
        }
    }

    // layer A: acc += H @ Wfused  (HT rowpairs broadcast, dup weights)
    const float* HTb = g_HT + (size_t)b * MH * NN;
    #pragma unroll 2
    for (int k = 0; k < MH; k++) {
        u64 av[4];
        #pragma unroll
        for (int rp = 0; rp < 4; rp++)
            av[rp] = *(const u64*)&HTb[k * NN + r0 + 2 * rp];
        const u64* wrow = (const u64*)&g_WfD[k * MH + kc];
        #pragma unroll
        for (int c = 0; c < 4; c++) {
            u64 wp = wrow[c];
            #pragma unroll
            for (int rp = 0; rp < 4; rp++)
                acc[rp][c] = fma2(av[rp], wp, acc[rp][c]);
        }
    }

    // silu -> transposed smem store (warp-private columns, pairs stay packed)
    #pragma unroll
    for (int rp = 0; rp < 4; rp++) {
        #pragma unroll
        for (int c = 0; c < 4; c++) {
            float2 q = upk(acc[rp][c]);
            *(u64*)&sbT[(kc + c) * 66 + r0 + 2 * rp] = pk(silu_f(q.x), silu_f(q.y));
        }
    }
    __syncwarp();

    // layer B: h2 = silu(h1 @ psi_w1 + psi_b1)
    {
        float4 bv = *(const float4*)&psi_b1[kc];
        float bb[4] = {bv.x, bv.y, bv.z, bv.w};
        #pragma unroll
        for (int rp = 0; rp < 4; rp++)
            #pragma unroll
            for (int c = 0; c < 4; c++)
                acc[rp][c] = pk(bb[c], bb[c]);
    }
    #pragma unroll 2
    for (int k = 0; k < MH; k++) {
        u64 av[4];
        #pragma unroll
        for (int rp = 0; rp < 4; rp++)
            av[rp] = *(const u64*)&sbT[k * 66 + r0 + 2 * rp];
        const u64* wrow = (const u64*)&g_W1D[k * MH + kc];
        #pragma unroll
        for (int c = 0; c < 4; c++) {
            u64 wp = wrow[c];
            #pragma unroll
            for (int rp = 0; rp < 4; rp++)
                acc[rp][c] = fma2(av[rp], wp, acc[rp][c]);
        }
    }

    // layer C: tanh(h2 @ psi_w2 + b2) * sp; rows warp-local -> shuffle reduce
    float w2v[4][3];
    #pragma unroll
    for (int c = 0; c < 4; c++)
        #pragma unroll
        for (int oc = 0; oc < 3; oc++)
            w2v[c][oc] = psi_w2[(kc + c) * 3 + oc];
    float bo[3] = {psi_b2[0], psi_b2[1], psi_b2[2]};
    float sp = g_sp;

    #pragma unroll
    for (int rp = 0; rp < 4; rp++) {
        float ha[4], hb[4];
        #pragma unroll
        for (int c = 0; c < 4; c++) {
            float2 q = upk(acc[rp][c]);
            ha[c] = silu_f(q.x);
            hb[c] = silu_f(q.y);
        }
        #pragma unroll
        for (int half = 0; half < 2; half++) {
            float* h = half ? hb : ha;
            int r = r0 + 2 * rp + half;
            #pragma unroll
            for (int oc = 0; oc < 3; oc++) {
                float p = h[0] * w2v[0][oc];
                p = fmaf(h[1], w2v[1][oc], p);
                p = fmaf(h[2], w2v[2][oc], p);
                p = fmaf(h[3], w2v[3][oc], p);
                #pragma unroll
                for (int off = 16; off; off >>= 1)
                    p += __shfl_xor_sync(0xffffffffu, p, off);
                if (l == 0)
                    out[((b * NN) + r) * 3 + oc] = tanhf(p + bo[oc]) * sp;
            }
        }
    }
}

// ---------------------------------------------------------------------------
// Inputs (metadata order): 0 x, 1 spin(unused), 2 phi_w0, 3 phi_b0, 4 phi_w1,
// 5 phi_b1, 6 psi_w0, 7 psi_b0, 8 psi_w1, 9 psi_b1, 10 psi_w2, 11 psi_b2,
// 12 bf_scale_raw. Output: float32 (512,64,3).
// ---------------------------------------------------------------------------
extern "C" void kernel_launch(void* const* d_in, const int* in_sizes, int n_in,
                              void* d_out, int out_size)
{
    const float* x      = (const float*)d_in[0];
    const float* phi_w0 = (const float*)d_in[2];
    const float* phi_b0 = (const float*)d_in[3];
    const float* phi_w1 = (const float*)d_in[4];
    const float* phi_b1 = (const float*)d_in[5];
    const float* psi_w0 = (const float*)d_in[6];
    const float* psi_b0 = (const float*)d_in[7];
    const float* psi_w1 = (const float*)d_in[8];
    const float* psi_b1 = (const float*)d_in[9];
    const float* psi_w2 = (const float*)d_in[10];
    const float* psi_b2 = (const float*)d_in[11];
    const float* bf     = (const float*)d_in[12];
    float* out = (float*)d_out;

    precompute_kernel<<<MH + 1, MH>>>(phi_w1, phi_b1, psi_w0, psi_b0, psi_w1, bf);
    phi_kernel<<<BB * 2, 256>>>(x, phi_w0, phi_b0);
    psi_kernel<<<BB, 256>>>(x, psi_w0, psi_b1, psi_w2, psi_b2, out);
}

// round 5
// speedup vs baseline: 1.8874x; 1.8874x over previous
#include <cuda_runtime.h>
#include <math.h>

#define BB 512
#define NN 64
#define MH 128

// ---- scratch (allocation-free) ----
// Packed tf32 weight pairs: g_WfP[(kt*4+q)*128 + n] = (Wf[kt*8+q][n], Wf[kt*8+q+4][n])
__device__ __align__(16) uint2 g_WfP[(MH / 8) * 4 * MH];   // 64KB
__device__ __align__(16) uint2 g_W1P[(MH / 8) * 4 * MH];   // 64KB
__device__ float g_c0[MH];     // psi_b0 + 63 * phi_b1 @ psi_w0[3:,:]
__device__ float g_sp;         // softplus(bf_scale_raw)

__device__ __forceinline__ float tanh_apx(float v) {
    float y; asm("tanh.approx.f32 %0, %1;" : "=f"(y) : "f"(v)); return y;
}
__device__ __forceinline__ float silu_f(float q) {
    float qh = 0.5f * q;
    float th = tanh_apx(qh);
    return fmaf(qh, th, qh);
}
__device__ __forceinline__ unsigned tf32r(float f) {
    unsigned u; asm("cvt.rna.tf32.f32 %0, %1;" : "=r"(u) : "f"(f)); return u;
}
__device__ __forceinline__ void mma_tf32(float c[4], unsigned a0, unsigned a1,
                                         unsigned a2, unsigned a3,
                                         unsigned b0, unsigned b1) {
    asm("mma.sync.aligned.m16n8k8.row.col.f32.tf32.tf32.f32 "
        "{%0,%1,%2,%3}, {%4,%5,%6,%7}, {%8,%9}, {%0,%1,%2,%3};"
        : "+f"(c[0]), "+f"(c[1]), "+f"(c[2]), "+f"(c[3])
        : "r"(a0), "r"(a1), "r"(a2), "r"(a3), "r"(b0), "r"(b1));
}

// ---------------------------------------------------------------------------
// Kernel 0: Wfused = phi_w1 @ psi_w0[3:]; pack Wfused & psi_w1 as tf32 pairs;
// c0 = psi_b0 + 63*phi_b1@psi_w0[3:]; sp = softplus(bf_scale_raw).
// ---------------------------------------------------------------------------
__global__ __launch_bounds__(128) void precompute_kernel(
    const float* __restrict__ phi_w1, const float* __restrict__ phi_b1,
    const float* __restrict__ psi_w0, const float* __restrict__ psi_b0,
    const float* __restrict__ psi_w1, const float* __restrict__ bf_scale_raw)
{
    __shared__ float row[MH];
    int t = threadIdx.x;
    int k = blockIdx.x;
    const float* src = (k < MH) ? (phi_w1 + k * MH) : phi_b1;
    row[t] = src[t];
    __syncthreads();

    float a0 = 0.f, a1 = 0.f, a2 = 0.f, a3 = 0.f;
    #pragma unroll 8
    for (int m = 0; m < MH; m += 4) {
        a0 = fmaf(row[m + 0], psi_w0[(3 + m + 0) * MH + t], a0);
        a1 = fmaf(row[m + 1], psi_w0[(3 + m + 1) * MH + t], a1);
        a2 = fmaf(row[m + 2], psi_w0[(3 + m + 2) * MH + t], a2);
        a3 = fmaf(row[m + 3], psi_w0[(3 + m + 3) * MH + t], a3);
    }
    float acc = (a0 + a1) + (a2 + a3);
    if (k < MH) {
        int kt = k >> 3, s = k & 7;
        unsigned wf = tf32r(acc);
        unsigned w1 = tf32r(psi_w1[k * MH + t]);
        int idx = (kt * 4 + (s & 3)) * MH + t;
        if (s < 4) { g_WfP[idx].x = wf; g_W1P[idx].x = w1; }
        else       { g_WfP[idx].y = wf; g_W1P[idx].y = w1; }
    } else {
        g_c0[t] = psi_b0[t] + 63.0f * acc;
        if (t == 0) {
            float v = bf_scale_raw[0];
            g_sp = (v > 20.0f) ? v : log1pf(__expf(v));
        }
    }
}

// ---------------------------------------------------------------------------
// Fused kernel: 512 blocks x 256 threads (8 warps).
// Phase 1 (phi, SIMT fp32): warp w owns rows w*8..+7, lane l owns ch 4l..4l+3.
//   H[i][k] = sum_{j!=i} silu(pre_ij) via halved-weight tanh form.
// Phase 2 (psi, tf32 mma.sync): H in shared (stride 132), two 128x128 GEMMs
//   on the tensor pipe, exact fp32 init & final projection.
// Shared: 48KB static, phase-aliased.
// ---------------------------------------------------------------------------
__global__ __launch_bounds__(256, 2) void fused_kernel(
    const float* __restrict__ x,
    const float* __restrict__ W0, const float* __restrict__ b0,
    const float* __restrict__ psi_w0, const float* __restrict__ psi_b1,
    const float* __restrict__ psi_w2, const float* __restrict__ psi_b2,
    float* __restrict__ out)
{
    __shared__ __align__(16) float smem_f[12288];   // 48KB
    float* vs  = smem_f;            // phase1: v'_j[k], 64x128
    float* r1s = smem_f + 8192;     // phase1: r1[j][i], 64x64
    float* sb  = smem_f;            // phase2: H / h1, 64 rows stride 132 (<=8444)
    float* part = smem_f + 8448;    // phase2: partials [2][64][3] = 384 floats

    int b = blockIdx.x;
    int t = threadIdx.x;
    int w = t >> 5, l = t & 31;
    int r0 = w * 8;
    int kc = l * 4;
    const float* xb = x + b * (NN * 3);

    // ---------------- Phase 1 setup ----------------
    for (int idx = t; idx < NN * MH; idx += 256) {
        int j = idx >> 7, k = idx & 127;
        float xj0 = xb[j * 3 + 0], xj1 = xb[j * 3 + 1], xj2 = xb[j * 3 + 2];
        float vv = xj0 * (W0[3 * MH + k] - W0[6 * MH + k]);
        vv = fmaf(xj1, W0[4 * MH + k] - W0[7 * MH + k], vv);
        vv = fmaf(xj2, W0[5 * MH + k] - W0[8 * MH + k], vv);
        vs[idx] = 0.5f * vv;
    }
    for (int idx = t; idx < NN * NN; idx += 256) {
        int j = idx >> 6, i = idx & 63;
        float d0 = xb[i * 3 + 0] - xb[j * 3 + 0];
        float d1 = xb[i * 3 + 1] - xb[j * 3 + 1];
        float d2 = xb[i * 3 + 2] - xb[j * 3 + 2];
        r1s[idx] = sqrtf(fmaf(d0, d0, fmaf(d1, d1, fmaf(d2, d2, 1e-12f))));
    }

    float w9h[4], w10h[4];
    float u[8][4];
    {
        float ws0[4], ws1[4], ws2[4], bh[4];
        #pragma unroll
        for (int c = 0; c < 4; c++) {
            int k = kc + c;
            ws0[c] = 0.5f * (W0[0 * MH + k] + W0[6 * MH + k]);
            ws1[c] = 0.5f * (W0[1 * MH + k] + W0[7 * MH + k]);
            ws2[c] = 0.5f * (W0[2 * MH + k] + W0[8 * MH + k]);
            w9h[c]  = 0.5f * W0[9 * MH + k];
            w10h[c] = 0.5f * W0[10 * MH + k];
            bh[c]  = 0.5f * b0[k];
        }
        #pragma unroll
        for (int ii = 0; ii < 8; ii++) {
            int i = r0 + ii;
            float xi0 = xb[i * 3 + 0], xi1 = xb[i * 3 + 1], xi2 = xb[i * 3 + 2];
            #pragma unroll
            for (int c = 0; c < 4; c++)
                u[ii][c] = fmaf(xi2, ws2[c],
                           fmaf(xi1, ws1[c], fmaf(xi0, ws0[c], bh[c])));
        }
    }
    __syncthreads();

    // ---------------- Phase 1 main loop ----------------
    float acc[8][4];
    #pragma unroll
    for (int ii = 0; ii < 8; ii++)
        #pragma unroll
        for (int c = 0; c < 4; c++) acc[ii][c] = 0.0f;

    const float4* vs4 = (const float4*)vs;
    #pragma unroll 2
    for (int j = 0; j < NN; j++) {
        float4 v4 = vs4[j * 32 + l];
        float vc[4] = {v4.x, v4.y, v4.z, v4.w};
        float4 ra = *(const float4*)&r1s[j * NN + r0];
        float4 rb = *(const float4*)&r1s[j * NN + r0 + 4];
        float r1v[8] = {ra.x, ra.y, ra.z, ra.w, rb.x, rb.y, rb.z, rb.w};
        #pragma unroll
        for (int ii = 0; ii < 8; ii++) {
            float r1 = r1v[ii];
            float r2 = fmaf(r1, r1, -1e-12f);
            #pragma unroll
            for (int c = 0; c < 4; c++) {
                float qh = fmaf(r1, w9h[c], fmaf(r2, w10h[c], u[ii][c] + vc[c]));
                float th = tanh_apx(qh);
                acc[ii][c] = fmaf(qh, th, acc[ii][c] + qh);
            }
        }
    }
    // subtract diagonal (same op order -> same rounding)
    #pragma unroll
    for (int ii = 0; ii < 8; ii++) {
        int ig = r0 + ii;
        float4 v4 = vs4[ig * 32 + l];
        float vc[4] = {v4.x, v4.y, v4.z, v4.w};
        float r1 = r1s[ig * NN + ig];
        float r2 = fmaf(r1, r1, -1e-12f);
        #pragma unroll
        for (int c = 0; c < 4; c++) {
            float qh = fmaf(r1, w9h[c], fmaf(r2, w10h[c], u[ii][c] + vc[c]));
            float th = tanh_apx(qh);
            acc[ii][c] -= fmaf(qh, th, qh);
        }
    }

    // ---------------- H -> shared (stride 132, conflict-free) ----------------
    __syncthreads();   // all phase-1 shared reads done
    #pragma unroll
    for (int ii = 0; ii < 8; ii++)
        *(float4*)&sb[(r0 + ii) * 132 + kc] =
            make_float4(acc[ii][0], acc[ii][1], acc[ii][2], acc[ii][3]);
    __syncthreads();

    // ---------------- Phase 2: psi via tf32 mma ----------------
    int mi = w & 3, nh = w >> 2;
    int gi = l >> 2, qi = l & 3;
    int rA = mi * 16 + gi;          // rows rA and rA+8
    int nbase = nh * 64;

    float C[8][4];
    float xr0[3] = {xb[rA * 3 + 0], xb[rA * 3 + 1], xb[rA * 3 + 2]};
    float xr1[3] = {xb[(rA + 8) * 3 + 0], xb[(rA + 8) * 3 + 1], xb[(rA + 8) * 3 + 2]};

    // C init: c0 + x @ psi_w0[0:3]  (exact fp32)
    #pragma unroll
    for (int tt = 0; tt < 8; tt++) {
        int nc = nbase + tt * 8 + qi * 2;
        #pragma unroll
        for (int h = 0; h < 2; h++) {
            float cc = g_c0[nc + h];
            float p0 = psi_w0[0 * MH + nc + h];
            float p1 = psi_w0[1 * MH + nc + h];
            float p2 = psi_w0[2 * MH + nc + h];
            C[tt][h]     = fmaf(xr0[2], p2, fmaf(xr0[1], p1, fmaf(xr0[0], p0, cc)));
            C[tt][2 + h] = fmaf(xr1[2], p2, fmaf(xr1[1], p1, fmaf(xr1[0], p0, cc)));
        }
    }

    // layer A: C += H @ Wfused
    {
        const float* sA0 = &sb[rA * 132];
        const float* sA1 = &sb[(rA + 8) * 132];
        const uint2* wp = &g_WfP[qi * MH + nbase + gi];
        #pragma unroll 1
        for (int kt = 0; kt < 16; kt++) {
            int k0 = kt * 8;
            unsigned a0 = tf32r(sA0[k0 + qi]);
            unsigned a1 = tf32r(sA1[k0 + qi]);
            unsigned a2 = tf32r(sA0[k0 + qi + 4]);
            unsigned a3 = tf32r(sA1[k0 + qi + 4]);
            #pragma unroll
            for (int tt = 0; tt < 8; tt++) {
                uint2 bb = wp[tt * 8];
                mma_tf32(C[tt], a0, a1, a2, a3, bb.x, bb.y);
            }
            wp += 4 * MH;
        }
    }
    __syncthreads();   // all H reads done before overwriting with h1

    // silu -> h1 in shared
    #pragma unroll
    for (int tt = 0; tt < 8; tt++) {
        int nc = nbase + tt * 8 + qi * 2;
        *(float2*)&sb[rA * 132 + nc] =
            make_float2(silu_f(C[tt][0]), silu_f(C[tt][1]));
        *(float2*)&sb[(rA + 8) * 132 + nc] =
            make_float2(silu_f(C[tt][2]), silu_f(C[tt][3]));
    }
    __syncthreads();

    // layer B: C = psi_b1 + h1 @ psi_w1
    #pragma unroll
    for (int tt = 0; tt < 8; tt++) {
        int nc = nbase + tt * 8 + qi * 2;
        float bb0 = psi_b1[nc], bb1 = psi_b1[nc + 1];
        C[tt][0] = bb0; C[tt][1] = bb1; C[tt][2] = bb0; C[tt][3] = bb1;
    }
    {
        const float* sA0 = &sb[rA * 132];
        const float* sA1 = &sb[(rA + 8) * 132];
        const uint2* wp = &g_W1P[qi * MH + nbase + gi];
        #pragma unroll 1
        for (int kt = 0; kt < 16; kt++) {
            int k0 = kt * 8;
            unsigned a0 = tf32r(sA0[k0 + qi]);
            unsigned a1 = tf32r(sA1[k0 + qi]);
            unsigned a2 = tf32r(sA0[k0 + qi + 4]);
            unsigned a3 = tf32r(sA1[k0 + qi + 4]);
            #pragma unroll
            for (int tt = 0; tt < 8; tt++) {
                uint2 bb = wp[tt * 8];
                mma_tf32(C[tt], a0, a1, a2, a3, bb.x, bb.y);
            }
            wp += 4 * MH;
        }
    }

    // layer C: silu -> partial projection onto psi_w2 (exact fp32)
    float p0[3] = {0.f, 0.f, 0.f}, p1[3] = {0.f, 0.f, 0.f};
    #pragma unroll
    for (int tt = 0; tt < 8; tt++) {
        int nc = nbase + tt * 8 + qi * 2;
        float s00 = silu_f(C[tt][0]), s01 = silu_f(C[tt][1]);
        float s10 = silu_f(C[tt][2]), s11 = silu_f(C[tt][3]);
        #pragma unroll
        for (int oc = 0; oc < 3; oc++) {
            float wa = psi_w2[nc * 3 + oc];
            float wb = psi_w2[(nc + 1) * 3 + oc];
            p0[oc] = fmaf(s01, wb, fmaf(s00, wa, p0[oc]));
            p1[oc] = fmaf(s11, wb, fmaf(s10, wa, p1[oc]));
        }
    }
    // quad reduce (lanes sharing gi): xor 1, xor 2
    #pragma unroll
    for (int oc = 0; oc < 3; oc++) {
        p0[oc] += __shfl_xor_sync(0xffffffffu, p0[oc], 1);
        p0[oc] += __shfl_xor_sync(0xffffffffu, p0[oc], 2);
        p1[oc] += __shfl_xor_sync(0xffffffffu, p1[oc], 1);
        p1[oc] += __shfl_xor_sync(0xffffffffu, p1[oc], 2);
    }
    if (qi == 0) {
        #pragma unroll
        for (int oc = 0; oc < 3; oc++) {
            part[nh * 192 + rA * 3 + oc] = p0[oc];
            part[nh * 192 + (rA + 8) * 3 + oc] = p1[oc];
        }
    }
    __syncthreads();

    // combine halves, tanh, scale, store
    if (t < 192) {
        int r = t / 3, oc = t - r * 3;
        float p = part[r * 3 + oc] + part[192 + r * 3 + oc] + psi_b2[oc];
        out[(b * NN + r) * 3 + oc] = tanhf(p) * g_sp;
    }
}

// ---------------------------------------------------------------------------
// Inputs (metadata order): 0 x, 1 spin(unused), 2 phi_w0, 3 phi_b0, 4 phi_w1,
// 5 phi_b1, 6 psi_w0, 7 psi_b0, 8 psi_w1, 9 psi_b1, 10 psi_w2, 11 psi_b2,
// 12 bf_scale_raw. Output: float32 (512,64,3).
// ---------------------------------------------------------------------------
extern "C" void kernel_launch(void* const* d_in, const int* in_sizes, int n_in,
                              void* d_out, int out_size)
{
    const float* x      = (const float*)d_in[0];
    const float* phi_w0 = (const float*)d_in[2];
    const float* phi_b0 = (const float*)d_in[3];
    const float* phi_w1 = (const float*)d_in[4];
    const float* phi_b1 = (const float*)d_in[5];
    const float* psi_w0 = (const float*)d_in[6];
    const float* psi_b0 = (const float*)d_in[7];
    const float* psi_w1 = (const float*)d_in[8];
    const float* psi_b1 = (const float*)d_in[9];
    const float* psi_w2 = (const float*)d_in[10];
    const float* psi_b2 = (const float*)d_in[11];
    const float* bf     = (const float*)d_in[12];
    float* out = (float*)d_out;

    precompute_kernel<<<MH + 1, MH>>>(phi_w1, phi_b1, psi_w0, psi_b0, psi_w1, bf);
    fused_kernel<<<BB, 256>>>(x, phi_w0, phi_b0, psi_w0,
                              psi_b1, psi_w2, psi_b2, out);
}